// round 9
// baseline (speedup 1.0000x reference)
#include <cuda_runtime.h>
#include <math.h>
#include <stdint.h>

#define B  4
#define NN 65536
#define KK 16
#define DD 32
#define NP 16384

// scratch
__device__ float  g_pool_t[(size_t)B * NN * DD];    // 33.6 MB  [b][n][d]
__device__ float  g_interp_t[(size_t)B * NP * DD];  //  8.4 MB  [b][np][d]
__device__ float4 g_xyz4[(size_t)B * NN];           //  4.2 MB  padded xyz

#define TB1   (B * (NN / 32))      // 8192  transpose feat_pool tiles
#define TB2   (B * (NP / 32))      // 2048  transpose feat_interp tiles
#define RELT  (B * NN * KK / 512)  // 8192  rel blocks total (512 pairs each)
#define RELA  5120                 // rel blocks in K1
#define RELBC 3072                 // rel blocks in K2 (RELT - RELA)
#define POOLB (B * (NP / 32))      // 2048  pool blocks
#define IB4   (B * (NN / 128))     // 2048  interp blocks (4 tiles each)

#define K0B  (B * NN / 1024)       // 256 xyz-pad blocks (1024 pts each)
#define K1B  (TB1 + TB2 + RELA)    // 15360 = 15*1024, period 3
#define K2B  (RELBC + POOLB + IB4) // 7168 = 7*1024, period 7

__device__ __forceinline__ uint32_t smem_u32(const void* p) {
    uint32_t a;
    asm("{ .reg .u64 t; cvta.to.shared.u64 t, %1; cvt.u32.u64 %0, t; }"
        : "=r"(a) : "l"(p));
    return a;
}

// ============ K0: pad xyz [B*N,3] -> float4, 1024 points / block ============
__global__ void __launch_bounds__(256) kernelX(const float* __restrict__ xyz) {
    __shared__ float s[3072];
    int tid = threadIdx.x;
    int p0 = blockIdx.x * 1024;
    const float4* src = (const float4*)(xyz + (size_t)p0 * 3);  // 768 float4
#pragma unroll
    for (int j = 0; j < 3; j++) {
        float4 v = __ldcs(&src[j * 256 + tid]);
        *(float4*)(s + (j * 256 + tid) * 4) = v;
    }
    __syncthreads();
#pragma unroll
    for (int j = 0; j < 4; j++) {
        int p = j * 256 + tid;
        g_xyz4[p0 + p] = make_float4(s[p * 3], s[p * 3 + 1], s[p * 3 + 2], 0.0f);
    }
}

// transpose one 32x32 tile of [B,32,M] -> [B,M,32]
__device__ __forceinline__ void do_transpose(float* sm, int tid, int tb,
                                             const float* feat_pool,
                                             const float* feat_interp) {
    float (*tile)[33] = (float (*)[33])sm;
    const float* in;
    float* outp;
    int M;
    if (tb < TB1) { in = feat_pool;   outp = g_pool_t;   M = NN; }
    else          { in = feat_interp; outp = g_interp_t; M = NP; tb -= TB1; }
    int mb = M / 32;
    int b  = tb / mb;
    int m0 = (tb - b * mb) * 32;
    int tx = tid & 31, ty = tid >> 5;
#pragma unroll
    for (int rr = 0; rr < 4; rr++) {
        int d = ty + 8 * rr;
        tile[d][tx] = __ldcs(&in[((size_t)(b * DD + d)) * M + m0 + tx]);
    }
    __syncthreads();
#pragma unroll
    for (int rr = 0; rr < 4; rr++) {
        int m = ty + 8 * rr;
        outp[((size_t)(b * M + m0 + m)) * DD + tx] = tile[tx][m];
    }
}

// rel block: 512 pairs, 2 pairs/thread, stage in smem, TMA bulk store
__device__ __forceinline__ void do_rel(float* smem, int tid, int rb,
                                       const int* __restrict__ nidx,
                                       float* __restrict__ out_rel) {
    int pbase = rb * 512;
    int b   = pbase >> 20;              // N*K = 2^20
    int bb  = b << 16;
    int nkb = pbase & 0xFFFFF;
    int t2  = tid * 2;

    int2 ii = __ldcs((const int2*)(nidx + pbase + t2));
    float4 Q0 = __ldg(&g_xyz4[bb + ii.x]);
    float4 Q1 = __ldg(&g_xyz4[bb + ii.y]);
    // pairs (2t, 2t+1) share n since t2 is even and K=16
    float4 P  = __ldg(&g_xyz4[bb + ((nkb + t2) >> 4)]);

    float rx0 = P.x - Q0.x, ry0 = P.y - Q0.y, rz0 = P.z - Q0.z;
    float d0 = sqrtf(rx0 * rx0 + ry0 * ry0 + rz0 * rz0);
    float rx1 = P.x - Q1.x, ry1 = P.y - Q1.y, rz1 = P.z - Q1.z;
    float d1 = sqrtf(rx1 * rx1 + ry1 * ry1 + rz1 * rz1);

    float4* sp = (float4*)(smem + tid * 20);
    sp[0] = make_float4(d0, rx0, ry0, rz0);
    sp[1] = make_float4(P.x, P.y, P.z, Q0.x);
    sp[2] = make_float4(Q0.y, Q0.z, d1, rx1);
    sp[3] = make_float4(ry1, rz1, P.x, P.y);
    sp[4] = make_float4(P.z, Q1.x, Q1.y, Q1.z);
    __syncthreads();

    asm volatile("fence.proxy.async.shared::cta;" ::: "memory");
    if (tid == 0) {
        uint32_t sa = smem_u32(smem);
        float* gp = out_rel + (size_t)rb * 5120;
        asm volatile(
            "cp.async.bulk.global.shared::cta.bulk_group [%0], [%1], %2;"
            :: "l"(gp), "r"(sa), "n"(20480) : "memory");
        asm volatile("cp.async.bulk.commit_group;" ::: "memory");
        asm volatile("cp.async.bulk.wait_group.read 0;" ::: "memory");
    }
    __syncthreads();
}

// ============ K1: transposes + rel chunk A (period 3) ============
__global__ void __launch_bounds__(256) kernel1(
    const float* __restrict__ feat_pool,
    const float* __restrict__ feat_interp,
    const int*   __restrict__ nidx,
    float* __restrict__ out_rel)
{
    __shared__ __align__(16) float smem[5120];   // 20 KB
    int bid = blockIdx.x;
    int tid = threadIdx.x;
    int r = bid % 3;
    int g = bid / 3;          // 0..5119

    if (r < 2) {
        do_transpose(smem, tid, 2 * g + r, feat_pool, feat_interp);
    } else {
        do_rel(smem, tid, g, nidx, out_rel);           // rel ids 0..5119
    }
}

// ============ K2: rel chunk B + pool + interp (period 7) ============
__global__ void __launch_bounds__(256) kernel2(
    const int* __restrict__ nidx,
    const int* __restrict__ pool_idx,
    const int* __restrict__ interp_idx,
    float* __restrict__ out_rel,
    float* __restrict__ out_pool,
    float* __restrict__ out_interp)
{
    __shared__ __align__(16) float smem[5120];   // 20 KB
    int bid = blockIdx.x;
    int tid = threadIdx.x;
    int r = bid % 7;
    int g = bid / 7;          // 0..1023

    if (r == 1 || r == 3 || r == 5) {
        do_rel(smem, tid, RELA + 3 * g + (r >> 1), nidx, out_rel);  // 5120..8191
    } else if (r == 0 || r == 4) {
        // -------- gather-max pooling --------
        float (*tile)[33] = (float (*)[33])smem;
        int pg = 2 * g + (r == 4);          // 0..2047
        int lane = tid & 31, w = tid >> 5;
        int row  = w * 4 + (lane >> 3);
        int dv   = lane & 7;
        int b   = pg / (NP / 32);
        int np0 = (pg - b * (NP / 32)) * 32;
        const int* ip = pool_idx + (b * NP + np0 + row) * KK;
        const float* basep = g_pool_t + (size_t)b * NN * DD;

        float4 m = make_float4(-INFINITY, -INFINITY, -INFINITY, -INFINITY);
#pragma unroll
        for (int kc = 0; kc < 4; kc++) {
            int4 q = __ldcs((const int4*)ip + kc);
            int qq[4] = {q.x, q.y, q.z, q.w};
#pragma unroll
            for (int j = 0; j < 4; j++) {
                float4 v = *(const float4*)(basep + qq[j] * DD + dv * 4);
                m.x = fmaxf(m.x, v.x); m.y = fmaxf(m.y, v.y);
                m.z = fmaxf(m.z, v.z); m.w = fmaxf(m.w, v.w);
            }
        }
        tile[row][dv * 4 + 0] = m.x;
        tile[row][dv * 4 + 1] = m.y;
        tile[row][dv * 4 + 2] = m.z;
        tile[row][dv * 4 + 3] = m.w;
        __syncthreads();
#pragma unroll
        for (int rr = 0; rr < 4; rr++) {
            int d = w + 8 * rr;
            __stcs(&out_pool[(size_t)(b * DD + d) * NP + np0 + lane], tile[lane][d]);
        }
    } else {
        // -------- nearest interpolation: 4 tiles / block --------
        float (*tile)[33] = (float (*)[33])smem;
        int ig = 2 * g + (r == 6);          // 0..2047
        int lane = tid & 31, w = tid >> 5;
        int row  = w * 4 + (lane >> 3);
        int dv   = lane & 7;
        int b  = ig / (NN / 128);
        int u0 = (ig - b * (NN / 128)) * 128;

        float4 v[4];
#pragma unroll
        for (int it = 0; it < 4; it++) {
            int i = __ldg(&interp_idx[b * NN + u0 + it * 32 + row]);
            v[it] = *(const float4*)(g_interp_t + ((size_t)(b * NP + i)) * DD + dv * 4);
        }
#pragma unroll
        for (int it = 0; it < 4; it++) {
            tile[it * 32 + row][dv * 4 + 0] = v[it].x;
            tile[it * 32 + row][dv * 4 + 1] = v[it].y;
            tile[it * 32 + row][dv * 4 + 2] = v[it].z;
            tile[it * 32 + row][dv * 4 + 3] = v[it].w;
        }
        __syncthreads();
#pragma unroll
        for (int it = 0; it < 4; it++) {
#pragma unroll
            for (int rr = 0; rr < 4; rr++) {
                int d = w + 8 * rr;
                __stcs(&out_interp[(size_t)(b * DD + d) * NN + u0 + it * 32 + lane],
                       tile[it * 32 + lane][d]);
            }
        }
    }
}

extern "C" void kernel_launch(void* const* d_in, const int* in_sizes, int n_in,
                              void* d_out, int out_size) {
    const float* xyz         = (const float*)d_in[0];   // [B,N,3]
    const int*   neigh_idx   = (const int*)  d_in[1];   // [B,N,K]
    const float* feat_pool   = (const float*)d_in[2];   // [B,32,N,1]
    const int*   pool_idx    = (const int*)  d_in[3];   // [B,Np,K]
    const float* feat_interp = (const float*)d_in[4];   // [B,32,Np,1]
    const int*   interp_idx  = (const int*)  d_in[5];   // [B,N,1]

    float* out = (float*)d_out;
    float* out_rel    = out;                                // B*N*K*10
    float* out_pool   = out + (size_t)B * NN * KK * 10;     // B*32*Np
    float* out_interp = out_pool + (size_t)B * DD * NP;     // B*32*N

    kernelX<<<K0B, 256>>>(xyz);
    kernel1<<<K1B, 256>>>(feat_pool, feat_interp, neigh_idx, out_rel);
    kernel2<<<K2B, 256>>>(neigh_idx, pool_idx, interp_idx,
                          out_rel, out_pool, out_interp);
}